// round 17
// baseline (speedup 1.0000x reference)
#include <cuda_runtime.h>
#include <cuda_bf16.h>
#include <cstdint>
#include <math.h>
#include <float.h>

#define NBATCH 8
#define TT 512
#define DIM 1024
#define NS 2048
#define NH 4
#define NKTOP 8
#define NDh 256
#define NGS 104             // scan grid: 32 topk + 8 writers + 64 corr
#define NROWS 4096
#define MAXH 16
#define LR_FAST 1.0f
#define LR_DEEP 0.1f
#define SURPRISE_TH 0.6f
#define DECAYF 0.9995f
#define INV_SQRT_DH 0.0625f
#define INV_SQRT_D  0.03125f

// scan smem layout (floats)
#define SM_WF 0              // 16384: 16 cols of fuse_W v-part, [8][1024] float2
#define SM_XC 16384          // 8192: h[cur] (corr phase) then v_t [8][1024]
#define SM_SMOD 24576        // 512 floats = 2048 bytes
#define SM_RED 25088         // 64
#define SM_LNG 25152         // 1024
#define SM_LNB 26176         // 1024
#define SMEM_FLOATS 27200
#define SMEM_BYTES (SMEM_FLOATS * 4)   // 108800

#define BM 128
#define BN 128
#define BK 32
#define PCH 10240
#define BUFSZ (4 * PCH)
#define GEMM_SMEM_BYTES (2 * BUFSZ)

__device__ float g_h[NROWS * DIM];
__device__ float g_y[NROWS * DIM];
__device__ float g_Vbuf[NS * DIM];
__device__ float g_Kmat[NS * DIM];
__device__ float g_vt[NBATCH * DIM];
__device__ float g_frall[(size_t)TT * NBATCH * DIM];
__device__ int   g_slot[NBATCH];
__device__ float g_lr[NBATCH];
__device__ float g_cpre[TT];
__device__ float g_cpost[TT];
__device__ int g_mask_kind;
// score decomposition (S0 only; corrections computed on the fly)
__device__ float g_S0[(size_t)NH * NROWS * NS];      // 128MB
__device__ float4 g_corr4[NBATCH * NS];
__device__ float  g_corrsum[NBATCH * NS];
__device__ float g_zero[4096];
// per-row state
__device__ float g_rm[NS];
__device__ float g_ra[NS];
__device__ int   g_rh[NS];            // history len; -1 = dense
__device__ float g_rg[NS][MAXH];
__device__ int   g_ri[NS][MAXH];
__device__ int   g_mlist[NS];
__device__ int   g_mcount;
__device__ unsigned char g_mflag[NS];
// flags
__device__ int g_fstate[8];
__device__ int g_fslot[8];
__device__ int g_fcorr[64];
__device__ int g_fvt[32];
__device__ int g_fC[64];
// bf16 buffers
__device__ __align__(16) __nv_bfloat16 g_hhi[NROWS * DIM];
__device__ __align__(16) __nv_bfloat16 g_hlo[NROWS * DIM];
__device__ __align__(16) __nv_bfloat16 g_thi[NROWS * 2 * DIM];
__device__ __align__(16) __nv_bfloat16 g_tlo[NROWS * 2 * DIM];
__device__ __align__(16) __nv_bfloat16 g_w1thi[2 * DIM * DIM];
__device__ __align__(16) __nv_bfloat16 g_w1tlo[2 * DIM * DIM];
__device__ __align__(16) __nv_bfloat16 g_w2thi[2 * DIM * DIM];
__device__ __align__(16) __nv_bfloat16 g_w2tlo[2 * DIM * DIM];
__device__ __align__(16) __nv_bfloat16 g_xhhi[(size_t)NROWS * DIM];
__device__ __align__(16) __nv_bfloat16 g_xhlo[(size_t)NROWS * DIM];
__device__ __align__(16) __nv_bfloat16 g_khhi[(size_t)NS * DIM];
__device__ __align__(16) __nv_bfloat16 g_khlo[(size_t)NS * DIM];

// ---- base-PTX helpers ----
__device__ __forceinline__ uint32_t smem_u32(const void* p) {
    uint32_t a;
    asm("{ .reg .u64 t; cvta.to.shared.u64 t, %1; cvt.u32.u64 %0, t; }" : "=r"(a) : "l"(p));
    return a;
}
__device__ __forceinline__ void cp_async16(uint32_t saddr, const void* gaddr) {
    asm volatile("cp.async.cg.shared.global [%0], [%1], 16;" :: "r"(saddr), "l"(gaddr));
}
__device__ __forceinline__ void cp_commit() { asm volatile("cp.async.commit_group;" ::: "memory"); }
__device__ __forceinline__ void cp_wait_all() { asm volatile("cp.async.wait_group 0;" ::: "memory"); }
__device__ __forceinline__ void ldmatrix_x4(uint32_t* r, uint32_t addr) {
    asm volatile("ldmatrix.sync.aligned.m8n8.x4.shared.b16 {%0,%1,%2,%3}, [%4];"
        : "=r"(r[0]), "=r"(r[1]), "=r"(r[2]), "=r"(r[3]) : "r"(addr));
}
__device__ __forceinline__ void ldmatrix_x2(uint32_t* r, uint32_t addr) {
    asm volatile("ldmatrix.sync.aligned.m8n8.x2.shared.b16 {%0,%1}, [%2];"
        : "=r"(r[0]), "=r"(r[1]) : "r"(addr));
}
__device__ __forceinline__ void mma16816(float* c, const uint32_t* a, const uint32_t* b) {
    asm volatile("mma.sync.aligned.m16n8k16.row.col.f32.bf16.bf16.f32 "
        "{%0,%1,%2,%3}, {%4,%5,%6,%7}, {%8,%9}, {%0,%1,%2,%3};"
        : "+f"(c[0]), "+f"(c[1]), "+f"(c[2]), "+f"(c[3])
        : "r"(a[0]), "r"(a[1]), "r"(a[2]), "r"(a[3]), "r"(b[0]), "r"(b[1]));
}
__device__ __forceinline__ void st_rel(int* p, int v) {
    asm volatile("st.release.gpu.global.s32 [%0], %1;" :: "l"(p), "r"(v) : "memory");
}
__device__ __forceinline__ int ld_acq(const int* p) {
    int v;
    asm volatile("ld.acquire.gpu.global.s32 %0, [%1];" : "=r"(v) : "l"(p) : "memory");
    return v;
}
__device__ __forceinline__ void wait_n(const int* flags, int n, int tgt, int tid) {
    for (;;) {
        int v = (tid < n) ? ld_acq(flags + tid) : tgt;
        if (__syncthreads_and(v >= tgt)) break;
    }
}

__device__ __forceinline__ float gelu_tanh(float x) {
    const float c = 0.7978845608028654f;
    float t = tanhf(c * (x + 0.044715f * x * x * x));
    return 0.5f * x * (1.0f + t);
}
__device__ __forceinline__ float blockSum256(float v, float* red, int tid) {
    #pragma unroll
    for (int o = 16; o; o >>= 1) v += __shfl_xor_sync(0xFFFFFFFFu, v, o);
    if ((tid & 31) == 0) red[tid >> 5] = v;
    __syncthreads();
    if (tid < 32) {
        float x = (tid < 8) ? red[tid] : 0.0f;
        #pragma unroll
        for (int o = 4; o; o >>= 1) x += __shfl_xor_sync(0xFFFFFFFFu, x, o);
        if (tid == 0) red[32] = x;
    }
    __syncthreads();
    float r = red[32];
    __syncthreads();
    return r;
}

// ---- packed (value desc, index asc) top-8 ----
__device__ __forceinline__ unsigned long long packkv(float v, int idx) {
    uint32_t u = __float_as_uint(v);
    uint32_t k = (u & 0x80000000u) ? ~u : (u | 0x80000000u);
    return ((unsigned long long)k << 32) | (uint32_t)(~idx);
}
__device__ __forceinline__ int unpack_idx(unsigned long long p) { return (int)(~(uint32_t)p); }
__device__ __forceinline__ float unpack_val(unsigned long long p) {
    uint32_t k = (uint32_t)(p >> 32);
    uint32_t u = (k & 0x80000000u) ? (k & 0x7FFFFFFFu) : ~k;
    return __uint_as_float(u);
}
#define PCE(x, y) { if (P[x] < P[y]) { unsigned long long _t = P[x]; P[x] = P[y]; P[y] = _t; } }
__device__ __forceinline__ void psort8(unsigned long long* P) {
    PCE(0,1) PCE(2,3) PCE(4,5) PCE(6,7)
    PCE(0,2) PCE(1,3) PCE(4,6) PCE(5,7)
    PCE(1,2) PCE(5,6)
    PCE(0,4) PCE(1,5) PCE(2,6) PCE(3,7)
    PCE(2,4) PCE(3,5)
    PCE(1,2) PCE(3,4) PCE(5,6)
}
__device__ __forceinline__ void pmerge8(unsigned long long* P, const unsigned long long* Q) {
    #pragma unroll
    for (int e = 0; e < 8; e++) { unsigned long long q = Q[7 - e]; if (P[e] < q) P[e] = q; }
    PCE(0,4) PCE(1,5) PCE(2,6) PCE(3,7)
    PCE(0,2) PCE(1,3) PCE(4,6) PCE(5,7)
    PCE(0,1) PCE(2,3) PCE(4,5) PCE(6,7)
}
__device__ __forceinline__ void pbfly(unsigned long long* P, int off) {
    unsigned long long Q[8];
    #pragma unroll
    for (int e = 0; e < 8; e++) Q[e] = __shfl_xor_sync(0xFFFFFFFFu, P[e], off);
    pmerge8(P, Q);
}

// ---- init: mask dtype + decay chain ----
__global__ void init_kernel(const unsigned char* __restrict__ mask) {
    __shared__ unsigned char anyf[TT];
    int tid = threadIdx.x;
    if (tid == 0) {
        const unsigned* w = (const unsigned*)mask;
        bool okf = true, oki = true, sawf = false, sawi = false;
        for (int i = 0; i < 1024; i++) {
            unsigned v = w[i];
            if (v == 0x3F800000u) sawf = true; else if (v != 0u) okf = false;
            if (v == 1u)          sawi = true; else if (v != 0u) oki = false;
        }
        int kind = 2;
        if (okf && sawf) kind = 0;
        else if (oki && sawi) kind = 1;
        g_mask_kind = kind;
    }
    __syncthreads();
    int kind = g_mask_kind;
    if (tid < TT) {
        bool any = false;
        for (int b = 0; b < NBATCH; b++) {
            int idx = b * TT + tid;
            bool m;
            if (kind == 0)      m = ((const float*)mask)[idx] != 0.0f;
            else if (kind == 1) m = ((const int*)mask)[idx] != 0;
            else                m = mask[idx] != 0;
            any = any || m;
        }
        anyf[tid] = any ? 1 : 0;
    }
    __syncthreads();
    if (tid == 0) {
        float c = 1.0f;
        for (int t = 0; t < TT; t++) {
            g_cpre[t] = c;
            if (anyf[t]) c *= DECAYF;
            g_cpost[t] = c;
        }
    }
}

// ---- state init ----
__global__ __launch_bounds__(256) void state_init() {
    int i = blockIdx.x * 256 + threadIdx.x;
    if (i < NS) { g_rm[i] = 1.0f; g_ra[i] = 1.0f; g_rh[i] = 0; g_mflag[i] = 0; }
    if (i < 4096) g_zero[i] = 0.0f;
    if (i < 8) { g_fstate[i] = 0; g_fslot[i] = 0; }
    if (i < 64) { g_fcorr[i] = 0; g_fC[i] = 0; }
    if (i < 32) g_fvt[i] = 0;
    if (i == 0) g_mcount = 0;
}

__global__ __launch_bounds__(256) void conv_split(const float* __restrict__ s,
                                                  __nv_bfloat16* __restrict__ hi,
                                                  __nv_bfloat16* __restrict__ lo, int n) {
    int i = blockIdx.x * 256 + threadIdx.x;
    if (i < n) {
        float v = s[i];
        __nv_bfloat16 h = __float2bfloat16_rn(v);
        hi[i] = h;
        lo[i] = __float2bfloat16_rn(v - __bfloat162float(h));
    }
}

// pack [R][1024] fp32 -> per-head [4][R][256] bf16 hi/lo
__global__ __launch_bounds__(256) void pack_heads(const float* __restrict__ src,
                                                  __nv_bfloat16* __restrict__ hi,
                                                  __nv_bfloat16* __restrict__ lo, int R) {
    int i = blockIdx.x * 256 + threadIdx.x;
    if (i < R * DIM) {
        int r = i >> 10, d = i & 1023;
        int h = d >> 8, c = d & 255;
        size_t o = ((size_t)h * R + r) * 256 + c;
        float v = src[i];
        __nv_bfloat16 hv = __float2bfloat16_rn(v);
        hi[o] = hv;
        lo[o] = __float2bfloat16_rn(v - __bfloat162float(hv));
    }
}

__global__ __launch_bounds__(256) void conv_T(const float* __restrict__ src,
                                              __nv_bfloat16* __restrict__ dhi,
                                              __nv_bfloat16* __restrict__ dlo,
                                              int R, int C) {
    __shared__ float t[32][33];
    int c0 = blockIdx.x * 32, r0 = blockIdx.y * 32;
    int tx = threadIdx.x & 31, ty = threadIdx.x >> 5;
    #pragma unroll
    for (int j = 0; j < 32; j += 8)
        t[ty + j][tx] = src[(size_t)(r0 + ty + j) * C + c0 + tx];
    __syncthreads();
    #pragma unroll
    for (int j = 0; j < 32; j += 8) {
        float v = t[tx][ty + j];
        __nv_bfloat16 h = __float2bfloat16_rn(v);
        __nv_bfloat16 l = __float2bfloat16_rn(v - __bfloat162float(h));
        size_t o = (size_t)(c0 + ty + j) * R + r0 + tx;
        dhi[o] = h; dlo[o] = l;
    }
}

// ---- mma.sync bf16-split GEMM ----
__device__ __forceinline__ void gemm_load_chunk(
    uint32_t sbuf, int tid, int m0, int n0, int c, int K,
    const __nv_bfloat16* __restrict__ Ahi, const __nv_bfloat16* __restrict__ Alo,
    const __nv_bfloat16* __restrict__ Bhi, const __nv_bfloat16* __restrict__ Blo)
{
    #pragma unroll
    for (int i = 0; i < 8; i++) {
        int idx = tid + i * 256;
        int piece = idx >> 9;
        int j = idx & 511;
        int row = j >> 2;
        int cv = (j & 3) * 8;
        const __nv_bfloat16* g;
        int grow;
        if (piece == 0)      { g = Ahi; grow = m0 + row; }
        else if (piece == 1) { g = Alo; grow = m0 + row; }
        else if (piece == 2) { g = Bhi; grow = n0 + row; }
        else                 { g = Blo; grow = n0 + row; }
        const void* ga = g + (size_t)grow * K + c * BK + cv;
        uint32_t sa = sbuf + (uint32_t)piece * PCH + (uint32_t)row * 80 + (uint32_t)cv * 2;
        cp_async16(sa, ga);
    }
    cp_commit();
}

template<int ACT>
__global__ __launch_bounds__(256) void gemm_mma(
    const __nv_bfloat16* __restrict__ Ahi, const __nv_bfloat16* __restrict__ Alo,
    const __nv_bfloat16* __restrict__ Bhi, const __nv_bfloat16* __restrict__ Blo,
    const float* __restrict__ bias, float* __restrict__ Cf,
    __nv_bfloat16* __restrict__ Chi, __nv_bfloat16* __restrict__ Clo,
    int K, int Ntot)
{
    extern __shared__ char smc[];
    int tid = threadIdx.x, lane = tid & 31, wid = tid >> 5;
    int wm = wid >> 2, wn = wid & 3;
    int m0 = blockIdx.y * BM, n0 = blockIdx.x * BN;
    int nch = K / BK;
    uint32_t sbase = smem_u32(smc);

    float acc[4][4][4];
    #pragma unroll
    for (int a = 0; a < 4; a++)
        #pragma unroll
        for (int b = 0; b < 4; b++)
            #pragma unroll
            for (int q = 0; q < 4; q++) acc[a][b][q] = 0.0f;

    gemm_load_chunk(sbase, tid, m0, n0, 0, K, Ahi, Alo, Bhi, Blo);
    cp_wait_all();
    __syncthreads();

    for (int c = 0; c < nch; c++) {
        int buf = c & 1;
        if (c + 1 < nch)
            gemm_load_chunk(sbase + (buf ^ 1) * BUFSZ, tid, m0, n0, c + 1, K,
                            Ahi, Alo, Bhi, Blo);
        uint32_t ab = sbase + (uint32_t)buf * BUFSZ;
        #pragma unroll
        for (int kk = 0; kk < 2; kk++) {
            int k0 = kk * 16;
            uint32_t bh[4][2], bl[4][2];
            #pragma unroll
            for (int ni = 0; ni < 4; ni++) {
                int nrow = wn * 32 + ni * 8 + (lane & 7);
                int ncol = k0 + ((lane >> 3) & 1) * 8;
                uint32_t ad = ab + 2 * PCH + (uint32_t)nrow * 80 + (uint32_t)ncol * 2;
                ldmatrix_x2(bh[ni], ad);
                ldmatrix_x2(bl[ni], ad + PCH);
            }
            #pragma unroll
            for (int mi = 0; mi < 4; mi++) {
                int arow = wm * 64 + mi * 16 + (lane & 7) + ((lane >> 3) & 1) * 8;
                int acol = k0 + ((lane >> 4) & 1) * 8;
                uint32_t ad = ab + (uint32_t)arow * 80 + (uint32_t)acol * 2;
                uint32_t ah[4], al[4];
                ldmatrix_x4(ah, ad);
                ldmatrix_x4(al, ad + PCH);
                #pragma unroll
                for (int ni = 0; ni < 4; ni++) {
                    mma16816(acc[mi][ni], ah, bh[ni]);
                    mma16816(acc[mi][ni], al, bh[ni]);
                    mma16816(acc[mi][ni], ah, bl[ni]);
                }
            }
        }
        cp_wait_all();
        __syncthreads();
    }

    #pragma unroll
    for (int mi = 0; mi < 4; mi++) {
        #pragma unroll
        for (int ni = 0; ni < 4; ni++) {
            int r = m0 + wm * 64 + mi * 16 + (lane >> 2);
            int cc = n0 + wn * 32 + ni * 8 + (lane & 3) * 2;
            float b0v = bias[cc], b1v = bias[cc + 1];
            float v0 = acc[mi][ni][0] + b0v, v1 = acc[mi][ni][1] + b1v;
            float v2 = acc[mi][ni][2] + b0v, v3 = acc[mi][ni][3] + b1v;
            if (ACT == 1) {
                v0 = gelu_tanh(v0); v1 = gelu_tanh(v1);
                v2 = gelu_tanh(v2); v3 = gelu_tanh(v3);
                __nv_bfloat16 h0 = __float2bfloat16_rn(v0);
                __nv_bfloat16 h1 = __float2bfloat16_rn(v1);
                __nv_bfloat16 h2 = __float2bfloat16_rn(v2);
                __nv_bfloat16 h3 = __float2bfloat16_rn(v3);
                __nv_bfloat16 l0 = __float2bfloat16_rn(v0 - __bfloat162float(h0));
                __nv_bfloat16 l1 = __float2bfloat16_rn(v1 - __bfloat162float(h1));
                __nv_bfloat16 l2 = __float2bfloat16_rn(v2 - __bfloat162float(h2));
                __nv_bfloat16 l3 = __float2bfloat16_rn(v3 - __bfloat162float(h3));
                uint32_t hp0 = (uint32_t)__bfloat16_as_ushort(h0) |
                               ((uint32_t)__bfloat16_as_ushort(h1) << 16);
                uint32_t hp1 = (uint32_t)__bfloat16_as_ushort(h2) |
                               ((uint32_t)__bfloat16_as_ushort(h3) << 16);
                uint32_t lp0 = (uint32_t)__bfloat16_as_ushort(l0) |
                               ((uint32_t)__bfloat16_as_ushort(l1) << 16);
                uint32_t lp1 = (uint32_t)__bfloat16_as_ushort(l2) |
                               ((uint32_t)__bfloat16_as_ushort(l3) << 16);
                *(uint32_t*)(Chi + (size_t)r * Ntot + cc) = hp0;
                *(uint32_t*)(Chi + (size_t)(r + 8) * Ntot + cc) = hp1;
                *(uint32_t*)(Clo + (size_t)r * Ntot + cc) = lp0;
                *(uint32_t*)(Clo + (size_t)(r + 8) * Ntot + cc) = lp1;
            } else {
                *(float2*)(Cf + (size_t)r * Ntot + cc) = make_float2(v0, v1);
                *(float2*)(Cf + (size_t)(r + 8) * Ntot + cc) = make_float2(v2, v3);
            }
        }
    }
}

// ---- LN + residual ----
__global__ __launch_bounds__(256) void ln_residual(const float* __restrict__ gam,
                                                   const float* __restrict__ bet) {
    __shared__ float red[40];
    int row = blockIdx.x, tid = threadIdx.x;
    const float* y = g_y + (size_t)row * DIM;
    float* h = g_h + (size_t)row * DIM;
    float xv[4], s = 0.0f;
    #pragma unroll
    for (int q = 0; q < 4; q++) { xv[q] = y[tid + q * 256]; s += xv[q]; }
    float mean = blockSum256(s, red, tid) * (1.0f / DIM);
    float vs = 0.0f;
    #pragma unroll
    for (int q = 0; q < 4; q++) { float d = xv[q] - mean; vs += d * d; }
    float var = blockSum256(vs, red, tid) * (1.0f / DIM);
    float rs = rsqrtf(var + 1e-5f);
    #pragma unroll
    for (int q = 0; q < 4; q++) {
        int d = tid + q * 256;
        h[d] += (xv[q] - mean) * rs * gam[d] + bet[d];
    }
}

// ---- post-pass: out = LN(frall + h) ----
__global__ __launch_bounds__(256) void ln_out(const float* __restrict__ gam,
                                              const float* __restrict__ bet,
                                              float* __restrict__ out) {
    __shared__ float red[40];
    int row = blockIdx.x, tid = threadIdx.x;
    int b = row / TT, t = row % TT;
    const float* fr = g_frall + ((size_t)t * NBATCH + b) * DIM;
    const float* h = g_h + (size_t)row * DIM;
    float xv[4], s = 0.0f;
    #pragma unroll
    for (int q = 0; q < 4; q++) {
        int d = tid + q * 256;
        xv[q] = fr[d] + h[d];
        s += xv[q];
    }
    float mean = blockSum256(s, red, tid) * (1.0f / DIM);
    float vs = 0.0f;
    #pragma unroll
    for (int q = 0; q < 4; q++) { float dd = xv[q] - mean; vs += dd * dd; }
    float var = blockSum256(vs, red, tid) * (1.0f / DIM);
    float rs = rsqrtf(var + 1e-5f);
    float* o = out + (size_t)row * DIM;
    #pragma unroll
    for (int q = 0; q < 4; q++) {
        int d = tid + q * 256;
        o[d] = (xv[q] - mean) * rs * gam[d] + bet[d];
    }
}

// 8-float dot of one head-slice chunk (2 float4 per lane)
__device__ __forceinline__ float dot8(const float4* A, const float* hc, int base4) {
    float4 a0 = A[base4], a1 = A[base4 + 1];
    float4 h0 = ((const float4*)hc)[base4], h1 = ((const float4*)hc)[base4 + 1];
    return a0.x*h0.x + a0.y*h0.y + a0.z*h0.z + a0.w*h0.w +
           a1.x*h1.x + a1.y*h1.y + a1.z*h1.z + a1.w*h1.w;
}

// ---- persistent scan ----
__global__ __launch_bounds__(256) void scan_kernel(
    const unsigned char* __restrict__ mask,
    const float* __restrict__ fuseW,
    const float* __restrict__ mlng, const float* __restrict__ mlnb)
{
    extern __shared__ float sm[];
    float* Wf  = sm + SM_WF;
    float* xc  = sm + SM_XC;
    unsigned char* smod = (unsigned char*)(sm + SM_SMOD);
    float* red = sm + SM_RED;
    unsigned long long* pred = (unsigned long long*)(sm + SM_RED);
    float* slng = sm + SM_LNG;
    float* slnb = sm + SM_LNB;
    int tid = threadIdx.x, cta = blockIdx.x;
    int wrp = tid >> 5, lan = tid & 31;

    if (cta < 64) {
        int c0 = cta * 16;
        float2* Wf2 = (float2*)Wf;
        for (int i = tid; i < 8192; i += 256) {
            int c2 = i >> 10, d = i & 1023;
            float2 v;
            v.x = fuseW[(size_t)(DIM + d) * DIM + c0 + 2 * c2];
            v.y = fuseW[(size_t)(DIM + d) * DIM + c0 + 2 * c2 + 1];
            Wf2[i] = v;
        }
    }
    for (int i = tid; i < 1024; i += 256) { slng[i] = mlng[i]; slnb[i] = mlnb[i]; }
    for (int i = tid; i < 2048; i += 256) smod[i] = 0;
    int kind = g_mask_kind;
    int last_mc = 0;
    __syncthreads();

    for (int t = 0; t < TT; t++) {
        float cpre = g_cpre[t], cpost = g_cpost[t];
        int tgt = t + 1;
        float* fr_t = g_frall + (size_t)t * NBATCH * DIM;

        if (cta >= 40) {
            // ---- correction CTAs: 8 per batch ----
            int c = cta - 40;
            int b = c >> 3, part = c & 7;
            int cur = b * TT + t;
            wait_n(g_fstate, 8, t, tid);
            ((float4*)xc)[tid] = ((const float4*)(g_h + (size_t)cur * DIM))[tid];
            __syncthreads();
            int mc = g_mcount;
            int wb = part * 8 + wrp;    // 0..63 warp slot within batch
            for (int i = wb; i < mc; i += 64) {
                int s = g_mlist[i];
                int L = g_rh[s];
                float a0 = 0.0f, a1 = 0.0f, a2 = 0.0f, a3 = 0.0f;
                if (L < 0) {
                    const float4* K = (const float4*)(g_Kmat + (size_t)s * DIM);
                    a0 = dot8(K, xc, 0 * 64 + lan * 2);
                    a1 = dot8(K, xc, 1 * 64 + lan * 2);
                    a2 = dot8(K, xc, 2 * 64 + lan * 2);
                    a3 = dot8(K, xc, 3 * 64 + lan * 2);
                } else {
                    for (int j = 0; j < L; j++) {
                        int idx = g_ri[s][j];
                        float g = g_rg[s][j];
                        const float4* H = (const float4*)(g_h + (size_t)idx * DIM);
                        a0 += g * dot8(H, xc, 0 * 64 + lan * 2);
                        a1 += g * dot8(H, xc, 1 * 64 + lan * 2);
                        a2 += g * dot8(H, xc, 2 * 64 + lan * 2);
                        a3 += g * dot8(H, xc, 3 * 64 + lan * 2);
                    }
                }
                #pragma unroll
                for (int o = 16; o; o >>= 1) {
                    a0 += __shfl_xor_sync(0xFFFFFFFFu, a0, o);
                    a1 += __shfl_xor_sync(0xFFFFFFFFu, a1, o);
                    a2 += __shfl_xor_sync(0xFFFFFFFFu, a2, o);
                    a3 += __shfl_xor_sync(0xFFFFFFFFu, a3, o);
                }
                if (lan == 0) {
                    float c0v, c1v, c2v, c3v;
                    if (L < 0) { c0v = a0; c1v = a1; c2v = a2; c3v = a3; }
                    else {
                        float m = g_rm[s], a = g_ra[s];
                        c0v = m * (a * g_S0[((size_t)0 * NROWS + cur) * NS + s] + a0);
                        c1v = m * (a * g_S0[((size_t)1 * NROWS + cur) * NS + s] + a1);
                        c2v = m * (a * g_S0[((size_t)2 * NROWS + cur) * NS + s] + a2);
                        c3v = m * (a * g_S0[((size_t)3 * NROWS + cur) * NS + s] + a3);
                    }
                    g_corr4[b * NS + s] = make_float4(c0v, c1v, c2v, c3v);
                    g_corrsum[b * NS + s] = c0v + c1v + c2v + c3v;
                }
            }
            __syncthreads();
            if (tid == 0) st_rel(&g_fcorr[c], tgt);
        } else if (cta < 32) {
            // ---- top-k CTA for (b, head) ----
            int b = cta >> 2, hh = cta & 3;
            int cur = b * TT + t;
            wait_n(g_fcorr, 64, tgt, tid);
            int mc = g_mcount;
            for (int i = last_mc + tid; i < mc; i += 256) smod[g_mlist[i]] = 1;
            last_mc = mc;
            __syncthreads();
            const float* sc = g_S0 + ((size_t)hh * NROWS + cur) * NS;
            float4 s0v = *(const float4*)(sc + tid * 8);
            float4 s1v = *(const float4*)(sc + tid * 8 + 4);
            float v8[8] = {s0v.x, s0v.y, s0v.z, s0v.w, s1v.x, s1v.y, s1v.z, s1v.w};
            unsigned long long P[8];
            #pragma unroll
            for (int e = 0; e < 8; e++) {
                int row = tid * 8 + e;
                float val = v8[e];
                if (smod[row]) {
                    float4 cv = g_corr4[b * NS + row];
                    val = (hh == 0) ? cv.x : (hh == 1) ? cv.y : (hh == 2) ? cv.z : cv.w;
                }
                P[e] = packkv(val * INV_SQRT_DH, row);
            }
            psort8(P);
            pbfly(P, 1); pbfly(P, 2); pbfly(P, 4); pbfly(P, 8); pbfly(P, 16);
            if (lan == 0) {
                #pragma unroll
                for (int e = 0; e < 8; e++) pred[wrp * 8 + e] = P[e];
            }
            __syncthreads();
            if (wrp == 0) {
                unsigned long long Q[8];
                if (lan < 8) {
                    #pragma unroll
                    for (int e = 0; e < 8; e++) Q[e] = pred[lan * 8 + e];
                } else {
                    #pragma unroll
                    for (int e = 0; e < 8; e++) Q[e] = 0ull;
                }
                pbfly(Q, 1); pbfly(Q, 2); pbfly(Q, 4);
                if (lan == 0) {
                    #pragma unroll
                    for (int e = 0; e < 8; e++) pred[e] = Q[e];
                }
            }
            __syncthreads();
            float topv[NKTOP]; int topi[NKTOP];
            #pragma unroll
            for (int e = 0; e < 8; e++) {
                unsigned long long pe = pred[e];
                topv[e] = unpack_val(pe); topi[e] = unpack_idx(pe);
            }
            float w8[NKTOP], Z = 0.0f;
            #pragma unroll
            for (int k = 0; k < NKTOP; k++) { w8[k] = expf(topv[k] - topv[0]); Z += w8[k]; }
            float invZ = 1.0f / Z;
            float accv = 0.0f;
            #pragma unroll
            for (int k = 0; k < NKTOP; k++)
                accv += w8[k] * g_Vbuf[(size_t)topi[k] * DIM + hh * NDh + tid];
            g_vt[b * DIM + hh * NDh + tid] = accv * invZ * cpre;
            __syncthreads();
            if (tid == 0) st_rel(&g_fvt[cta], tgt);
        } else {
            // ---- sw-argmax CTA (writer) for batch b = cta-32 ----
            int b = cta - 32;
            int cur = b * TT + t;
            wait_n(g_fcorr, 64, tgt, tid);
            int mc = g_mcount;
            for (int i = last_mc + tid; i < mc; i += 256) smod[g_mlist[i]] = 1;
            last_mc = mc;
            __syncthreads();
            float v8[8];
            #pragma unroll
            for (int e = 0; e < 8; e++) {
                int row = tid * 8 + e;
                float base;
                if (smod[row]) base = g_corrsum[b * NS + row];
                else {
                    base = 0.0f;
                    #pragma unroll
                    for (int h = 0; h < NH; h++)
                        base += g_S0[((size_t)h * NROWS + cur) * NS + row];
                }
                v8[e] = base * INV_SQRT_D;
            }
            unsigned long long best = packkv(v8[0], tid * 8);
            #pragma unroll
            for (int k = 1; k < 8; k++) {
                unsigned long long c = packkv(v8[k], tid * 8 + k);
                if (c > best) best = c;
            }
            #pragma unroll
            for (int o = 16; o; o >>= 1) {
                unsigned long long c = __shfl_xor_sync(0xFFFFFFFFu, best, o);
                if (c > best) best = c;
            }
            if (lan == 0) pred[wrp] = best;
            __syncthreads();
            if (tid == 0) {
                unsigned long long m = pred[0];
                for (int k = 1; k < 8; k++) if (pred[k] > m) m = pred[k];
                pred[8] = m;
            }
            __syncthreads();
            unsigned long long m = pred[8];
            float mv = unpack_val(m);
            __syncthreads();
            float se = 0.0f;
            #pragma unroll
            for (int k = 0; k < 8; k++) se += expf(v8[k] - mv);
            float Z = blockSum256(se, red, tid);
            if (tid == 0) {
                float surprise = 1.0f - 1.0f / Z;
                int midx = b * TT + t;
                float mk;
                if (kind == 0)      mk = ((const float*)mask)[midx];
                else if (kind == 1) mk = (float)((const int*)mask)[midx];
                else                mk = (float)mask[midx];
                float lr = (surprise > SURPRISE_TH ? LR_FAST : LR_DEEP);
                lr *= (mk != 0.0f ? 1.0f : 0.0f);
                g_slot[b] = unpack_idx(m);
                g_lr[b] = lr;
                st_rel(&g_fslot[b], tgt);
            }
            __syncthreads();
        }

        // ---- C CTAs (0..63): wait v_t, compute 16 fused columns ----
        if (cta < 64) {
            wait_n(g_fvt, 32, tgt, tid);
            for (int i = tid; i < 2048; i += 256)
                ((float4*)xc)[i] = ((const float4*)g_vt)[i];
            __syncthreads();
            {
                int b = wrp;
                const float2* Wf2 = (const float2*)Wf;
                float A[16];
                #pragma unroll
                for (int c2 = 0; c2 < 16; c2++) A[c2] = 0.0f;
                for (int j = 0; j < 32; j++) {
                    int d = j * 32 + lan;
                    float x = xc[b * 1024 + d];
                    #pragma unroll
                    for (int c2 = 0; c2 < 8; c2++) {
                        float2 wv = Wf2[c2 * 1024 + d];
                        A[2 * c2] += x * wv.x;
                        A[2 * c2 + 1] += x * wv.y;
                    }
                }
                #pragma unroll
                for (int o = 16; o; o >>= 1)
                    #pragma unroll
                    for (int c2 = 0; c2 < 16; c2++)
                        A[c2] += __shfl_xor_sync(0xFFFFFFFFu, A[c2], o);
                if (lan == 0) {
                    int c0 = cta * 16;
                    const float* fh = g_y + (size_t)(b * TT + t) * DIM + c0;
                    #pragma unroll
                    for (int c2 = 0; c2 < 16; c2++)
                        fr_t[b * DIM + c0 + c2] = A[c2] + fh[c2];
                }
            }
            __syncthreads();
            if (tid == 0) st_rel(&g_fC[cta], tgt);
        }

        // ---- writers: E phase ----
        if (cta >= 32 && cta < 40) {
            int b = cta - 32;
            wait_n(g_fslot, 8, tgt, tid);
            wait_n(g_fC, 64, tgt, tid);
            int slots[8]; float lrs[8];
            #pragma unroll
            for (int b2 = 0; b2 < 8; b2++) { slots[b2] = g_slot[b2]; lrs[b2] = g_lr[b2]; }
            int myslot = slots[b];
            int lowest = 8;
            #pragma unroll
            for (int b2 = 0; b2 < 8; b2++)
                if (slots[b2] == myslot && b2 < lowest) lowest = b2;
            if (b == lowest) {
                float L = 0.0f;
                #pragma unroll
                for (int b2 = 0; b2 < 8; b2++)
                    if (slots[b2] == myslot) L += lrs[b2];
                if (L != 0.0f) {
                    int s = myslot;
                    #pragma unroll 1
                    for (int b2 = 0; b2 < 8; b2++) {
                        if (slots[b2] != s || lrs[b2] == 0.0f) continue;
                        const float* hb = g_h + (size_t)(b2 * TT + t) * DIM;
                        const float* fb = fr_t + b2 * DIM;
                        float sx = 0.0f, xv[4];
                        #pragma unroll
                        for (int q = 0; q < 4; q++) {
                            int d = tid + q * 256;
                            xv[q] = fb[d] + hb[d];
                            sx += xv[q];
                        }
                        float mean = blockSum256(sx, red, tid) * (1.0f / DIM);
                        float vsum = 0.0f;
                        #pragma unroll
                        for (int q = 0; q < 4; q++) { float dd = xv[q] - mean; vsum += dd * dd; }
                        float var = blockSum256(vsum, red, tid) * (1.0f / DIM);
                        if (tid == 0) { red[40 + b2] = mean; red[48 + b2] = rsqrtf(var + 1e-5f); }
                    }
                    __syncthreads();
                    float invcp = 1.0f / cpost;
                    #pragma unroll
                    for (int q = 0; q < 4; q++) {
                        int d = tid + q * 256;
                        float vpre = g_Vbuf[(size_t)s * DIM + d];
                        float kpre = g_Kmat[(size_t)s * DIM + d];
                        float va = 0.0f, knew = (1.0f - L) * kpre;
                        #pragma unroll
                        for (int b2 = 0; b2 < 8; b2++) {
                            if (slots[b2] != s || lrs[b2] == 0.0f) continue;
                            float hv = g_h[(size_t)(b2 * TT + t) * DIM + d];
                            float f = fr_t[b2 * DIM + d] + hv;
                            float vw = (f - red[40 + b2]) * red[48 + b2] * slng[d] + slnb[d];
                            va += lrs[b2] * invcp * (vw - cpost * vpre);
                            knew += lrs[b2] * hv;
                        }
                        g_Vbuf[(size_t)s * DIM + d] = vpre + va;
                        g_Kmat[(size_t)s * DIM + d] = knew;
                    }
                    if (tid == 0) {
                        if (!g_mflag[s]) {
                            g_mflag[s] = 1;
                            int pos = atomicAdd(&g_mcount, 1);
                            g_mlist[pos] = s;
                        }
                        int Lh = g_rh[s];
                        if (Lh >= 0) {
                            int nnew = 0;
                            #pragma unroll
                            for (int b2 = 0; b2 < 8; b2++)
                                if (slots[b2] == s && lrs[b2] != 0.0f) nnew++;
                            float mnew = (1.0f - L) * g_rm[s];
                            if (mnew == 0.0f) {
                                g_rm[s] = 1.0f; g_ra[s] = 0.0f;
                                int j = 0;
                                #pragma unroll
                                for (int b2 = 0; b2 < 8; b2++) {
                                    if (slots[b2] == s && lrs[b2] != 0.0f) {
                                        g_rg[s][j] = lrs[b2];
                                        g_ri[s][j] = b2 * TT + t;
                                        j++;
                                    }
                                }
                                g_rh[s] = j;
                            } else if (Lh + nnew > MAXH) {
                                g_rh[s] = -1;
                            } else {
                                g_rm[s] = mnew;
                                int j = Lh;
                                #pragma unroll
                                for (int b2 = 0; b2 < 8; b2++) {
                                    if (slots[b2] == s && lrs[b2] != 0.0f) {
                                        g_rg[s][j] = lrs[b2] / mnew;
                                        g_ri[s][j] = b2 * TT + t;
                                        j++;
                                    }
                                }
                                g_rh[s] = j;
                            }
                        }
                    }
                }
            }
            __syncthreads();
            if (tid == 0) st_rel(&g_fstate[b], tgt);
        }
        __syncthreads();
    }
}

// ---- launch ----
extern "C" void kernel_launch(void* const* d_in, const int* in_sizes, int n_in,
                              void* d_out, int out_size) {
    const float* x      = (const float*)d_in[0];
    const unsigned char* mask = (const unsigned char*)d_in[1];
    const float* W1     = (const float*)d_in[2];
    const float* b1     = (const float*)d_in[3];
    const float* W2     = (const float*)d_in[4];
    const float* b2     = (const float*)d_in[5];
    const float* ln_g   = (const float*)d_in[6];
    const float* ln_b   = (const float*)d_in[7];
    const float* fuse_W = (const float*)d_in[8];
    const float* fuse_b = (const float*)d_in[9];
    const float* mln_g  = (const float*)d_in[10];
    const float* mln_b  = (const float*)d_in[11];
    const float* mem_K  = (const float*)d_in[12];
    const float* mem_V  = (const float*)d_in[13];
    float* out = (float*)d_out;

    float *p_h, *p_y, *p_V, *p_Km, *p_S0, *p_z;
    __nv_bfloat16 *p_hhi, *p_hlo, *p_thi, *p_tlo, *p_w1h, *p_w1l, *p_w2h, *p_w2l;
    __nv_bfloat16 *p_xhh, *p_xhl, *p_khh, *p_khl;
    cudaGetSymbolAddress((void**)&p_h, g_h);
    cudaGetSymbolAddress((void**)&p_y, g_y);
    cudaGetSymbolAddress((void**)&p_V, g_Vbuf);
    cudaGetSymbolAddress((void**)&p_Km, g_Kmat);
    cudaGetSymbolAddress((void**)&p_S0, g_S0);
    cudaGetSymbolAddress((void**)&p_z, g_zero);
    cudaGetSymbolAddress((void**)&p_hhi, g_hhi);
    cudaGetSymbolAddress((void**)&p_hlo, g_hlo);
    cudaGetSymbolAddress((void**)&p_thi, g_thi);
    cudaGetSymbolAddress((void**)&p_tlo, g_tlo);
    cudaGetSymbolAddress((void**)&p_w1h, g_w1thi);
    cudaGetSymbolAddress((void**)&p_w1l, g_w1tlo);
    cudaGetSymbolAddress((void**)&p_w2h, g_w2thi);
    cudaGetSymbolAddress((void**)&p_w2l, g_w2tlo);
    cudaGetSymbolAddress((void**)&p_xhh, g_xhhi);
    cudaGetSymbolAddress((void**)&p_xhl, g_xhlo);
    cudaGetSymbolAddress((void**)&p_khh, g_khhi);
    cudaGetSymbolAddress((void**)&p_khl, g_khlo);

    cudaMemcpyAsync(p_h, x, (size_t)NROWS * DIM * 4, cudaMemcpyDeviceToDevice, 0);
    cudaMemcpyAsync(p_V, mem_V, (size_t)NS * DIM * 4, cudaMemcpyDeviceToDevice, 0);
    cudaMemcpyAsync(p_Km, mem_K, (size_t)NS * DIM * 4, cudaMemcpyDeviceToDevice, 0);
    init_kernel<<<1, 512>>>(mask);
    state_init<<<16, 256>>>();

    cudaFuncSetAttribute(gemm_mma<1>, cudaFuncAttributeMaxDynamicSharedMemorySize, GEMM_SMEM_BYTES);
    cudaFuncSetAttribute(gemm_mma<0>, cudaFuncAttributeMaxDynamicSharedMemorySize, GEMM_SMEM_BYTES);

    const int M = NROWS;
    for (int i = 0; i < 2; i++) {
        conv_split<<<(M * DIM + 255) / 256, 256>>>(p_h, p_hhi, p_hlo, M * DIM);
        conv_T<<<dim3(2 * DIM / 32, DIM / 32), 256>>>(
            W1 + (size_t)i * DIM * 2 * DIM, p_w1h, p_w1l, DIM, 2 * DIM);
        gemm_mma<1><<<dim3(2 * DIM / BN, M / BM), 256, GEMM_SMEM_BYTES>>>(
            p_hhi, p_hlo, p_w1h, p_w1l, b1 + (size_t)i * 2 * DIM,
            nullptr, p_thi, p_tlo, DIM, 2 * DIM);
        conv_T<<<dim3(DIM / 32, 2 * DIM / 32), 256>>>(
            W2 + (size_t)i * 2 * DIM * DIM, p_w2h, p_w2l, 2 * DIM, DIM);
        gemm_mma<0><<<dim3(DIM / BN, M / BM), 256, GEMM_SMEM_BYTES>>>(
            p_thi, p_tlo, p_w2h, p_w2l, b2 + (size_t)i * DIM,
            p_y, nullptr, nullptr, 2 * DIM, DIM);
        ln_residual<<<M, 256>>>(ln_g + (size_t)i * DIM, ln_b + (size_t)i * DIM);
    }

    // fused_h = h @ fuse_W[0:1024] + fuse_b  (into g_y)
    conv_split<<<(M * DIM + 255) / 256, 256>>>(p_h, p_hhi, p_hlo, M * DIM);
    conv_T<<<dim3(DIM / 32, DIM / 32), 256>>>(fuse_W, p_w1h, p_w1l, DIM, DIM);
    gemm_mma<0><<<dim3(DIM / BN, M / BM), 256, GEMM_SMEM_BYTES>>>(
        p_hhi, p_hlo, p_w1h, p_w1l, fuse_b, p_y, nullptr, nullptr, DIM, DIM);

    // score precompute: per-head packs + S0 (no Gram)
    pack_heads<<<(M * DIM + 255) / 256, 256>>>(p_h, p_xhh, p_xhl, M);
    pack_heads<<<(NS * DIM + 255) / 256, 256>>>(mem_K, p_khh, p_khl, NS);
    for (int h = 0; h < NH; h++) {
        size_t xo = (size_t)h * M * NDh, ko = (size_t)h * NS * NDh;
        gemm_mma<0><<<dim3(NS / BN, M / BM), 256, GEMM_SMEM_BYTES>>>(
            p_xhh + xo, p_xhl + xo, p_khh + ko, p_khl + ko, p_z,
            p_S0 + (size_t)h * M * NS, nullptr, nullptr, NDh, NS);
    }

    cudaFuncSetAttribute(scan_kernel, cudaFuncAttributeMaxDynamicSharedMemorySize, SMEM_BYTES);
    scan_kernel<<<NGS, 256, SMEM_BYTES>>>(mask, fuse_W, mln_g, mln_b);

    ln_out<<<M, 256>>>(mln_g, mln_b, out);
}